// round 10
// baseline (speedup 1.0000x reference)
#include <cuda_runtime.h>
#include <cstdint>

#define N_NODES 100000
#define N_EDGES 1600000
#define IN_DIM  256
#define HID_DIM 64
#define OUT_DIM 64

// -------- scratch (device globals: allocation-free per harness rules) --------
__device__ __align__(16) float g_ew[N_EDGES];        // normalized edge weights
__device__ __align__(16) float g_norm[N_EDGES];      // dinv[row]*ew*dinv[col]
__device__ __align__(16) float g_deg[N_NODES];       // degree (init 1.0 self-loop)
__device__ __align__(16) float g_dinv[N_NODES];      // deg^{-1/2}
__device__ __align__(16) float g_y1[N_NODES * HID_DIM];   // x @ W1
__device__ __align__(16) float g_agg1[N_NODES * HID_DIM]; // layer-1 aggregation
__device__ __align__(16) float g_y2[N_NODES * OUT_DIM];   // h @ W2
__device__ __align__(16) float g_agg2[N_NODES * OUT_DIM]; // layer-2 aggregation
__device__ int g_min, g_max;
__device__ int g_ei64, g_ec64;   // 1 if buffer really is int64, 0 if int32

// flag-selected integer load (handles JAX silently demoting int64 -> int32)
__device__ __forceinline__ long long ld_int(const void* p, long long i, int is64) {
    if (is64) return ((const long long*)p)[i];
    return (long long)((const int*)p)[i];
}

// ---- Blackwell packed f32x2 helpers (exact fp32, 2 FMAs per instruction) ----
__device__ __forceinline__ unsigned long long ffma2(
    unsigned long long a, unsigned long long b, unsigned long long c) {
    unsigned long long d;
    asm("fma.rn.f32x2 %0, %1, %2, %3;" : "=l"(d) : "l"(a), "l"(b), "l"(c));
    return d;
}
__device__ __forceinline__ unsigned long long pack2(float v) {
    unsigned long long d;
    asm("mov.b64 %0, {%1, %1};" : "=l"(d) : "f"(v));
    return d;
}
__device__ __forceinline__ float2 unpack2(unsigned long long v) {
    float2 r;
    asm("mov.b64 {%0, %1}, %2;" : "=f"(r.x), "=f"(r.y) : "l"(v));
    return r;
}

// ------------------------------- prep kernels -------------------------------
__global__ void k_init() {
    int i = blockIdx.x * blockDim.x + threadIdx.x;
    if (i < N_NODES) g_deg[i] = 1.0f;               // self-loop weight 1
    if (i == 0) {
        g_min = 0x7fffffff; g_max = (int)0x80000000;
        g_ei64 = 1; g_ec64 = 1;
    }
}

__global__ void k_detect(const void* ei, const void* ec) {
    int bad_ei = 0, bad_ec = 0;
    for (int i = threadIdx.x; i < 4096; i += blockDim.x) {
        long long v = ((const long long*)ei)[i];
        if (v < 0 || v >= N_NODES) bad_ei = 1;
        long long w = ((const long long*)ec)[i];
        if (w < 0 || w >= (1LL << 20)) bad_ec = 1;
    }
    if (bad_ei) atomicAnd(&g_ei64, 0);
    if (bad_ec) atomicAnd(&g_ec64, 0);
}

__global__ void k_minmax(const void* __restrict__ ec) {
    int is64 = g_ec64;
    int lmin = 0x7fffffff, lmax = (int)0x80000000;
    for (int e = blockIdx.x * blockDim.x + threadIdx.x; e < N_EDGES;
         e += gridDim.x * blockDim.x) {
        int v = (int)ld_int(ec, e, is64);
        lmin = min(lmin, v);
        lmax = max(lmax, v);
    }
    #pragma unroll
    for (int o = 16; o; o >>= 1) {
        lmin = min(lmin, __shfl_xor_sync(0xffffffffu, lmin, o));
        lmax = max(lmax, __shfl_xor_sync(0xffffffffu, lmax, o));
    }
    if ((threadIdx.x & 31) == 0) {
        atomicMin(&g_min, lmin);
        atomicMax(&g_max, lmax);
    }
}

__global__ void k_ew_deg(const void* __restrict__ ec,
                         const void* __restrict__ ei) {
    int e = blockIdx.x * blockDim.x + threadIdx.x;
    if (e >= N_EDGES) return;
    float mn = (float)g_min;
    float inv = 1.0f / ((float)g_max - mn);
    float w = ((float)(int)ld_int(ec, e, g_ec64) - mn) * inv;
    g_ew[e] = w;
    int c = (int)ld_int(ei, (long long)N_EDGES + e, g_ei64);
    if ((unsigned)c < (unsigned)N_NODES) atomicAdd(&g_deg[c], w);
}

__global__ void k_dinv() {
    int i = blockIdx.x * blockDim.x + threadIdx.x;
    if (i >= N_NODES) return;
    float d = g_deg[i];
    g_dinv[i] = d > 0.0f ? rsqrtf(d) : 0.0f;
}

__global__ void k_norm(const void* __restrict__ ei) {
    int e = blockIdx.x * blockDim.x + threadIdx.x;
    if (e >= N_EDGES) return;
    int is64 = g_ei64;
    int r = (int)ld_int(ei, e, is64);
    int c = (int)ld_int(ei, (long long)N_EDGES + e, is64);
    float nrm = 0.0f;
    if ((unsigned)r < (unsigned)N_NODES && (unsigned)c < (unsigned)N_NODES)
        nrm = g_dinv[r] * g_ew[e] * g_dinv[c];
    g_norm[e] = nrm;
}

// --------------------------------- GEMM -------------------------------------
// Tiled smem GEMM, packed f32x2 FMAs, no shuffles.
// Block: 256 threads -> 64 rows x 64 cols. Thread: 2 rows x 8 cols.
// LAYER 1: y1 = x @ W1 (K=256), epilogue also writes agg1 = y1*dinv^2.
// LAYER 2: y2 = relu(agg1+b1) @ W2 (K=64), epilogue writes agg2 = y2*dinv^2.
template <int LAYER>
__global__ void k_gemm(const float* __restrict__ x_ext,
                       const float* __restrict__ W,
                       const float* __restrict__ bias) {
    constexpr int K   = (LAYER == 1) ? IN_DIM : HID_DIM;
    constexpr int NCH = K / 64;
    __shared__ float sX[64 * 68];                 // [row][k], stride 68
    __shared__ __align__(16) float sW[64 * 64];   // [k][col]

    int tid = threadIdx.x;
    int row_base = blockIdx.x * 64;
    int ry = tid >> 3;        // 0..31 row-pair
    int cx = tid & 7;         // 0..7 col-group
    int r0 = 2 * ry;
    int c0 = cx * 8;

    unsigned long long acc[2][4];
    #pragma unroll
    for (int a = 0; a < 2; a++)
        #pragma unroll
        for (int b = 0; b < 4; b++) acc[a][b] = 0ull;

    int t16 = tid & 15, tg = tid >> 4;  // staging coords
    int kk4 = t16 * 4;

    for (int ch = 0; ch < NCH; ch++) {
        // ---- stage x tile: 64 rows x 64 k ----
        #pragma unroll
        for (int i = 0; i < 4; i++) {
            int lrow = tg + 16 * i;
            int grow = row_base + lrow;
            float4 v = make_float4(0.f, 0.f, 0.f, 0.f);
            if (grow < N_NODES) {
                if (LAYER == 1) {
                    v = *(const float4*)(x_ext + (size_t)grow * K + ch * 64 + kk4);
                } else {
                    float4 a = *(const float4*)(g_agg1 + (size_t)grow * K + kk4);
                    float4 b = *(const float4*)(bias + kk4);
                    v.x = fmaxf(a.x + b.x, 0.f);
                    v.y = fmaxf(a.y + b.y, 0.f);
                    v.z = fmaxf(a.z + b.z, 0.f);
                    v.w = fmaxf(a.w + b.w, 0.f);
                }
            }
            *(float4*)(sX + lrow * 68 + kk4) = v;
        }
        // ---- stage W tile: 64 k x 64 cols ----
        #pragma unroll
        for (int i = 0; i < 4; i++) {
            int wk = tg + 16 * i;
            *(float4*)(sW + wk * 64 + kk4) =
                *(const float4*)(W + (size_t)(ch * 64 + wk) * 64 + kk4);
        }
        __syncthreads();

        // ---- compute ----
        #pragma unroll 8
        for (int k = 0; k < 64; k++) {
            unsigned long long pa = pack2(sX[r0 * 68 + k]);
            unsigned long long pb = pack2(sX[(r0 + 1) * 68 + k]);
            const ulonglong2* wp = (const ulonglong2*)(sW + k * 64 + c0);
            ulonglong2 wA = wp[0];  // cols c0..c3 (2 packed pairs)
            ulonglong2 wB = wp[1];  // cols c4..c7
            acc[0][0] = ffma2(wA.x, pa, acc[0][0]);
            acc[0][1] = ffma2(wA.y, pa, acc[0][1]);
            acc[0][2] = ffma2(wB.x, pa, acc[0][2]);
            acc[0][3] = ffma2(wB.y, pa, acc[0][3]);
            acc[1][0] = ffma2(wA.x, pb, acc[1][0]);
            acc[1][1] = ffma2(wA.y, pb, acc[1][1]);
            acc[1][2] = ffma2(wB.x, pb, acc[1][2]);
            acc[1][3] = ffma2(wB.y, pb, acc[1][3]);
        }
        __syncthreads();
    }

    // ---- epilogue: write y and agg = y*dinv^2 (self-loop init) ----
    float* y   = (LAYER == 1) ? g_y1   : g_y2;
    float* agg = (LAYER == 1) ? g_agg1 : g_agg2;
    #pragma unroll
    for (int rr = 0; rr < 2; rr++) {
        int rg = row_base + r0 + rr;
        if (rg >= N_NODES) continue;
        float d = g_dinv[rg];
        float s = d * d;
        float2 p0 = unpack2(acc[rr][0]);
        float2 p1 = unpack2(acc[rr][1]);
        float2 p2 = unpack2(acc[rr][2]);
        float2 p3 = unpack2(acc[rr][3]);
        float4 v0 = make_float4(p0.x, p0.y, p1.x, p1.y);
        float4 v1 = make_float4(p2.x, p2.y, p3.x, p3.y);
        *(float4*)(y + (size_t)rg * 64 + c0)     = v0;
        *(float4*)(y + (size_t)rg * 64 + c0 + 4) = v1;
        float4 a0 = make_float4(v0.x * s, v0.y * s, v0.z * s, v0.w * s);
        float4 a1 = make_float4(v1.x * s, v1.y * s, v1.z * s, v1.w * s);
        *(float4*)(agg + (size_t)rg * 64 + c0)     = a0;
        *(float4*)(agg + (size_t)rg * 64 + c0 + 4) = a1;
    }
}

// ------------------------------ edge scatter ---------------------------------
// 16 lanes per edge, float4 per lane: gather y[row], scale, ONE vector RED
// (atomicAdd float4) per lane -> 16 L2 atomic ops/edge.
template <int LAYER>
__global__ void k_scatter(const void* __restrict__ ei) {
    int t = blockIdx.x * blockDim.x + threadIdx.x;
    int e = t >> 4;
    int l = t & 15;
    if (e >= N_EDGES) return;
    int is64 = g_ei64;
    int r = (int)ld_int(ei, e, is64);
    int c = (int)ld_int(ei, (long long)N_EDGES + e, is64);
    if ((unsigned)r >= (unsigned)N_NODES || (unsigned)c >= (unsigned)N_NODES)
        return;
    float nrm = g_norm[e];
    float4 v;
    float4* dst;
    if constexpr (LAYER == 1) {
        v = ((const float4*)g_y1)[r * 16 + l];
        dst = (float4*)(g_agg1 + c * 64 + 4 * l);
    } else {
        v = ((const float4*)g_y2)[r * 16 + l];
        dst = (float4*)(g_agg2 + c * 64 + 4 * l);
    }
    float4 s;
    s.x = v.x * nrm; s.y = v.y * nrm; s.z = v.z * nrm; s.w = v.w * nrm;
    atomicAdd(dst, s);   // sm_90+: single RED.E.ADD.v4.F32
}

// --------------------- finalize: bias2 + log_softmax -------------------------
__global__ void k_final(const float* __restrict__ b2, float* __restrict__ out,
                        int write_lsm) {
    int t = blockIdx.x * blockDim.x + threadIdx.x;
    int i = t >> 5;
    int lane = t & 31;
    if (i >= N_NODES) return;
    float2 v = ((const float2*)g_agg2)[i * 32 + lane];
    v.x += b2[2 * lane];
    v.y += b2[2 * lane + 1];
    ((float2*)out)[i * 32 + lane] = v;  // node_embeddings
    if (!write_lsm) return;
    float m = fmaxf(v.x, v.y);
    #pragma unroll
    for (int o = 16; o; o >>= 1) m = fmaxf(m, __shfl_xor_sync(0xffffffffu, m, o));
    float s = expf(v.x - m) + expf(v.y - m);
    #pragma unroll
    for (int o = 16; o; o >>= 1) s += __shfl_xor_sync(0xffffffffu, s, o);
    float lse = m + logf(s);
    float2 o2; o2.x = v.x - lse; o2.y = v.y - lse;
    ((float2*)(out + (size_t)N_NODES * OUT_DIM))[i * 32 + lane] = o2;
}

// --------------------------------- launch ------------------------------------
extern "C" void kernel_launch(void* const* d_in, const int* in_sizes, int n_in,
                              void* d_out, int out_size) {
    const float* x = nullptr;
    const void *ei = nullptr, *ec = nullptr;
    const float *W1 = nullptr, *b1 = nullptr, *W2 = nullptr, *b2 = nullptr;
    for (int i = 0; i < n_in; i++) {
        int s = in_sizes[i];
        if (s == N_NODES * IN_DIM)       x  = (const float*)d_in[i];
        else if (s == 2 * N_EDGES)       ei = d_in[i];
        else if (s == N_EDGES)           ec = d_in[i];
        else if (s == IN_DIM * HID_DIM)  W1 = (const float*)d_in[i];
        else if (s == HID_DIM * OUT_DIM) W2 = (const float*)d_in[i];
        else if (s == HID_DIM) {
            if (!b1) b1 = (const float*)d_in[i];
            else     b2 = (const float*)d_in[i];
        }
    }
    float* out = (float*)d_out;
    if (!x || !ei || !ec || !W1 || !b1 || !W2 || !b2) return;

    int write_lsm = (out_size >= 2 * N_NODES * OUT_DIM) ? 1 : 0;
    int gemm_blocks = (N_NODES + 63) / 64;

    k_init<<<(N_NODES + 255) / 256, 256>>>();
    k_detect<<<1, 256>>>(ei, ec);
    k_minmax<<<512, 256>>>(ec);
    k_ew_deg<<<(N_EDGES + 255) / 256, 256>>>(ec, ei);
    k_dinv<<<(N_NODES + 255) / 256, 256>>>();
    k_norm<<<(N_EDGES + 255) / 256, 256>>>(ei);

    // layer 1: y1 = x@W1 (+ agg1 = y1*dinv^2 self-loop), then edge scatter
    k_gemm<1><<<gemm_blocks, 256>>>(x, W1, b1);
    k_scatter<1><<<(N_EDGES * 16 + 255) / 256, 256>>>(ei);

    // layer 2: y2 = relu(agg1+b1)@W2 (+ agg2 = y2*dinv^2), then edge scatter
    k_gemm<2><<<gemm_blocks, 256>>>(x, W2, b1);
    k_scatter<2><<<(N_EDGES * 16 + 255) / 256, 256>>>(ei);

    // finalize: + b2 -> embeddings, log_softmax -> second half of d_out
    k_final<<<(N_NODES * 32 + 255) / 256, 256>>>(b2, out, write_lsm);
}

// round 11
// speedup vs baseline: 1.1932x; 1.1932x over previous
#include <cuda_runtime.h>
#include <cstdint>

#define N_NODES 100000
#define N_EDGES 1600000
#define IN_DIM  256
#define HID_DIM 64
#define OUT_DIM 64

#define GEMM1_BLOCKS (N_NODES / 32)            // 3125
#define EWDEG_BLOCKS ((N_EDGES + 255) / 256)   // 6250

// -------- scratch (device globals: allocation-free per harness rules) --------
__device__ __align__(16) float g_ew[N_EDGES];        // normalized edge weights
__device__ __align__(16) float g_deg[N_NODES];       // degree (init 1.0 self-loop)
__device__ __align__(16) float g_dinv[N_NODES];      // deg^{-1/2}
__device__ __align__(16) float g_y1[N_NODES * HID_DIM];   // x @ W1
__device__ __align__(16) float g_agg1[N_NODES * HID_DIM]; // edge-only aggregation L1
__device__ __align__(16) float g_y2[N_NODES * OUT_DIM];   // h @ W2
__device__ __align__(16) float g_agg2[N_NODES * OUT_DIM]; // edge-only aggregation L2
__device__ int g_min, g_max;
__device__ int g_ei64, g_ec64;   // 1 if buffer really is int64, 0 if int32

// flag-selected integer load (handles JAX silently demoting int64 -> int32)
__device__ __forceinline__ long long ld_int(const void* p, long long i, int is64) {
    if (is64) return ((const long long*)p)[i];
    return (long long)((const int*)p)[i];
}

// ------------------------------- prep kernels -------------------------------
// init deg=1 (self-loop), flags, and ZERO both agg buffers (scatter targets).
__global__ void k_init() {
    int t = blockIdx.x * blockDim.x + threadIdx.x;
    const int Q = N_NODES * HID_DIM / 4;  // float4 count per agg buffer
    if (t < Q)          ((float4*)g_agg1)[t] = make_float4(0.f, 0.f, 0.f, 0.f);
    else if (t < 2 * Q) ((float4*)g_agg2)[t - Q] = make_float4(0.f, 0.f, 0.f, 0.f);
    if (t < N_NODES) g_deg[t] = 1.0f;
    if (t == 0) {
        g_min = 0x7fffffff; g_max = (int)0x80000000;
        g_ei64 = 1; g_ec64 = 1;
    }
}

__global__ void k_detect(const void* ei, const void* ec) {
    int bad_ei = 0, bad_ec = 0;
    for (int i = threadIdx.x; i < 4096; i += blockDim.x) {
        long long v = ((const long long*)ei)[i];
        if (v < 0 || v >= N_NODES) bad_ei = 1;
        long long w = ((const long long*)ec)[i];
        if (w < 0 || w >= (1LL << 20)) bad_ec = 1;
    }
    if (bad_ei) atomicAnd(&g_ei64, 0);
    if (bad_ec) atomicAnd(&g_ec64, 0);
}

__global__ void k_minmax(const void* __restrict__ ec) {
    int is64 = g_ec64;
    int lmin = 0x7fffffff, lmax = (int)0x80000000;
    for (int e = blockIdx.x * blockDim.x + threadIdx.x; e < N_EDGES;
         e += gridDim.x * blockDim.x) {
        int v = (int)ld_int(ec, e, is64);
        lmin = min(lmin, v);
        lmax = max(lmax, v);
    }
    #pragma unroll
    for (int o = 16; o; o >>= 1) {
        lmin = min(lmin, __shfl_xor_sync(0xffffffffu, lmin, o));
        lmax = max(lmax, __shfl_xor_sync(0xffffffffu, lmax, o));
    }
    if ((threadIdx.x & 31) == 0) {
        atomicMin(&g_min, lmin);
        atomicMax(&g_max, lmax);
    }
}

__global__ void k_dinv() {
    int i = blockIdx.x * blockDim.x + threadIdx.x;
    if (i >= N_NODES) return;
    float d = g_deg[i];
    g_dinv[i] = d > 0.0f ? rsqrtf(d) : 0.0f;
}

// ------------------- device-side GEMM bodies (shuffle, R6) -------------------
// LAYER 1: y1 = x @ W1 (K=256).  LAYER 2: y2 = relu(agg1 + y1*dinv^2 + b1) @ W2.
// 256 threads = 8 warps, 4 rows/warp -> 32 rows/block. Writes y only.
template <int LAYER>
__device__ __forceinline__ void gemm_body(int blk,
                                          const float* __restrict__ x_ext,
                                          const float* __restrict__ W,
                                          const float* __restrict__ bias) {
    constexpr int K  = (LAYER == 1) ? IN_DIM : HID_DIM;
    constexpr int KC = (LAYER == 1) ? 128 : 64;
    __shared__ __align__(16) float2 sW[128 * 32];  // max chunk (32 KB)

    int warp = threadIdx.x >> 5, lane = threadIdx.x & 31;
    int row0 = (blk * 8 + warp) * 4;

    float xr[4][K / 32];
    #pragma unroll
    for (int r = 0; r < 4; r++) {
        int row = row0 + r;
        float s = 0.0f;
        if (LAYER == 2) { float di = g_dinv[row]; s = di * di; }
        #pragma unroll
        for (int j = 0; j < K / 32; j++) {
            float v;
            if (LAYER == 1) {
                v = x_ext[(size_t)row * K + j * 32 + lane];
            } else {
                int idx = row * K + j * 32 + lane;
                v = g_agg1[idx] + g_y1[idx] * s + bias[j * 32 + lane];
                v = fmaxf(v, 0.0f);
            }
            xr[r][j] = v;
        }
    }

    float2 acc[4];
    #pragma unroll
    for (int r = 0; r < 4; r++) { acc[r].x = 0.0f; acc[r].y = 0.0f; }

    #pragma unroll
    for (int ch = 0; ch < K / KC; ch++) {
        {
            const float4* Wv = (const float4*)(W + ch * KC * 64);
            float4* sWv = (float4*)sW;
            for (int i = threadIdx.x; i < KC * 16; i += 256) sWv[i] = Wv[i];
        }
        __syncthreads();

        #pragma unroll
        for (int j = 0; j < KC / 32; j++) {
            int jj = ch * (KC / 32) + j;
            #pragma unroll 8
            for (int kk = 0; kk < 32; kk++) {
                float2 w = sW[(j * 32 + kk) * 32 + lane];
                #pragma unroll
                for (int r = 0; r < 4; r++) {
                    float xv = __shfl_sync(0xffffffffu, xr[r][jj], kk);
                    acc[r].x += xv * w.x;
                    acc[r].y += xv * w.y;
                }
            }
        }
        __syncthreads();
    }

    #pragma unroll
    for (int r = 0; r < 4; r++) {
        int row = row0 + r;
        if constexpr (LAYER == 1)
            ((float2*)g_y1)[row * 32 + lane] = acc[r];
        else
            ((float2*)g_y2)[row * 32 + lane] = acc[r];
    }
}

// fused launch: blocks [0, GEMM1_BLOCKS) run GEMM1, the rest run ew+deg.
// (GEMM1 is independent of the edge chain; ew_deg hides under it.)
__global__ void k_gemm1_ewdeg(const float* __restrict__ x,
                              const float* __restrict__ W1,
                              const void* __restrict__ ec,
                              const void* __restrict__ ei) {
    if (blockIdx.x < GEMM1_BLOCKS) {
        gemm_body<1>(blockIdx.x, x, W1, nullptr);
        return;
    }
    int e = (blockIdx.x - GEMM1_BLOCKS) * blockDim.x + threadIdx.x;
    if (e >= N_EDGES) return;
    float mn = (float)g_min;
    float inv = 1.0f / ((float)g_max - mn);
    float w = ((float)(int)ld_int(ec, e, g_ec64) - mn) * inv;
    g_ew[e] = w;
    int c = (int)ld_int(ei, (long long)N_EDGES + e, g_ei64);
    if ((unsigned)c < (unsigned)N_NODES) atomicAdd(&g_deg[c], w);
}

__global__ void k_gemm2(const float* __restrict__ W2,
                        const float* __restrict__ b1) {
    gemm_body<2>(blockIdx.x, nullptr, W2, b1);
}

// ------------------------------ edge scatter ---------------------------------
// 16 lanes per edge, float4 per lane; norm computed inline (no k_norm pass).
template <int LAYER>
__global__ void k_scatter(const void* __restrict__ ei) {
    int t = blockIdx.x * blockDim.x + threadIdx.x;
    int e = t >> 4;
    int l = t & 15;
    if (e >= N_EDGES) return;
    int is64 = g_ei64;
    int r = (int)ld_int(ei, e, is64);
    int c = (int)ld_int(ei, (long long)N_EDGES + e, is64);
    if ((unsigned)r >= (unsigned)N_NODES || (unsigned)c >= (unsigned)N_NODES)
        return;
    float nrm = g_dinv[r] * g_ew[e] * g_dinv[c];
    float4 v;
    float4* dst;
    if constexpr (LAYER == 1) {
        v = ((const float4*)g_y1)[r * 16 + l];
        dst = (float4*)(g_agg1 + c * 64 + 4 * l);
    } else {
        v = ((const float4*)g_y2)[r * 16 + l];
        dst = (float4*)(g_agg2 + c * 64 + 4 * l);
    }
    float4 s;
    s.x = v.x * nrm; s.y = v.y * nrm; s.z = v.z * nrm; s.w = v.w * nrm;
    atomicAdd(dst, s);   // sm_90+: single RED.E.ADD.v4.F32
}

// ------------- finalize: self-loop + bias2 + log_softmax --------------------
__global__ void k_final(const float* __restrict__ b2, float* __restrict__ out,
                        int write_lsm) {
    int t = blockIdx.x * blockDim.x + threadIdx.x;
    int i = t >> 5;
    int lane = t & 31;
    if (i >= N_NODES) return;
    float di = g_dinv[i];
    float sl = di * di;
    float2 a = ((const float2*)g_agg2)[i * 32 + lane];
    float2 y = ((const float2*)g_y2)[i * 32 + lane];
    float2 v;
    v.x = a.x + y.x * sl + b2[2 * lane];
    v.y = a.y + y.y * sl + b2[2 * lane + 1];
    ((float2*)out)[i * 32 + lane] = v;  // node_embeddings
    if (!write_lsm) return;
    float m = fmaxf(v.x, v.y);
    #pragma unroll
    for (int o = 16; o; o >>= 1) m = fmaxf(m, __shfl_xor_sync(0xffffffffu, m, o));
    float s = expf(v.x - m) + expf(v.y - m);
    #pragma unroll
    for (int o = 16; o; o >>= 1) s += __shfl_xor_sync(0xffffffffu, s, o);
    float lse = m + logf(s);
    float2 o2; o2.x = v.x - lse; o2.y = v.y - lse;
    ((float2*)(out + (size_t)N_NODES * OUT_DIM))[i * 32 + lane] = o2;
}

// --------------------------------- launch ------------------------------------
extern "C" void kernel_launch(void* const* d_in, const int* in_sizes, int n_in,
                              void* d_out, int out_size) {
    const float* x = nullptr;
    const void *ei = nullptr, *ec = nullptr;
    const float *W1 = nullptr, *b1 = nullptr, *W2 = nullptr, *b2 = nullptr;
    for (int i = 0; i < n_in; i++) {
        int s = in_sizes[i];
        if (s == N_NODES * IN_DIM)       x  = (const float*)d_in[i];
        else if (s == 2 * N_EDGES)       ei = d_in[i];
        else if (s == N_EDGES)           ec = d_in[i];
        else if (s == IN_DIM * HID_DIM)  W1 = (const float*)d_in[i];
        else if (s == HID_DIM * OUT_DIM) W2 = (const float*)d_in[i];
        else if (s == HID_DIM) {
            if (!b1) b1 = (const float*)d_in[i];
            else     b2 = (const float*)d_in[i];
        }
    }
    float* out = (float*)d_out;
    if (!x || !ei || !ec || !W1 || !b1 || !W2 || !b2) return;

    int write_lsm = (out_size >= 2 * N_NODES * OUT_DIM) ? 1 : 0;

    // init covers 2 * (N_NODES*64/4) float4 zero-stores
    int init_threads = 2 * (N_NODES * HID_DIM / 4);
    k_init<<<(init_threads + 255) / 256, 256>>>();
    k_detect<<<1, 256>>>(ei, ec);
    k_minmax<<<512, 256>>>(ec);

    // GEMM1 (independent) fused with ew+deg edge pass in ONE launch
    k_gemm1_ewdeg<<<GEMM1_BLOCKS + EWDEG_BLOCKS, 256>>>(x, W1, ec, ei);
    k_dinv<<<(N_NODES + 255) / 256, 256>>>();

    // layer 1 edge aggregation (agg1 = edge messages only)
    k_scatter<1><<<(N_EDGES * 16 + 255) / 256, 256>>>(ei);

    // layer 2: y2 = relu(agg1 + y1*dinv^2 + b1) @ W2, then edge aggregation
    k_gemm2<<<GEMM1_BLOCKS, 256>>>(W2, b1);
    k_scatter<2><<<(N_EDGES * 16 + 255) / 256, 256>>>(ei);

    // finalize: self-loop + b2 -> embeddings, log_softmax -> second half
    k_final<<<(N_NODES * 32 + 255) / 256, 256>>>(b2, out, write_lsm);
}